// round 1
// baseline (speedup 1.0000x reference)
#include <cuda_runtime.h>
#include <cstdint>

#define OUTD 11008
#define IND  4096
#define GCNT 704512
#define CDIM 172
#define NBATCH 8

// ---------------------------------------------------------------------------
// Kernel 1: out[b, o] = bias[o]   (out is poisoned 0xAA; atomics add onto this)
// ---------------------------------------------------------------------------
__global__ void init_out_kernel(const float* __restrict__ bias,
                                float* __restrict__ out) {
    int idx = blockIdx.x * blockDim.x + threadIdx.x;
    if (idx < NBATCH * OUTD) out[idx] = bias[idx % OUTD];
}

// packed f32x2 helpers (sm_100+)
__device__ __forceinline__ void fma2(unsigned long long& acc,
                                     unsigned long long a,
                                     unsigned long long b) {
    asm("fma.rn.f32x2 %0, %1, %2, %0;" : "+l"(acc) : "l"(a), "l"(b));
}
__device__ __forceinline__ unsigned long long pack2(float v) {
    unsigned long long r;
    asm("mov.b64 %0, {%1, %1};" : "=l"(r) : "f"(v));
    return r;
}

// ---------------------------------------------------------------------------
// Kernel 2: main dequant-GEMV.
// Block = (c, i-chunk of 1024). 8 warps split the i-chunk (128 i each).
// Lane l owns W_q row l -> outputs o_hi = l*172+c, o_lo = (l+32)*172+c.
// ---------------------------------------------------------------------------
__global__ __launch_bounds__(256) void hqq_gemv_kernel(
    const int*   __restrict__ Wq,     // [32, 704512] int32, one packed byte each
    const float* __restrict__ scale,  // [704512]
    const float* __restrict__ zero,   // [704512]
    const float* __restrict__ x,      // [8, 4096]
    float*       __restrict__ out)    // [8, 11008]
{
    __shared__ unsigned long long sm[4096];            // 32 KB
    float* xs = reinterpret_cast<float*>(sm);          // xs[j][b] : 1024 x 8

    const int tid = threadIdx.x;
    const int c   = blockIdx.x >> 2;                   // 0..171
    const int h   = blockIdx.x & 3;                    // i-chunk index
    const int ib  = h << 10;                           // i base of chunk

    // Stage x chunk transposed to [i][batch] so batch pairs are contiguous.
    #pragma unroll
    for (int r = 0; r < 32; ++r) {
        int idx = tid + (r << 8);                      // 0..8191
        int b = idx >> 10, j = idx & 1023;
        xs[(j << 3) + b] = x[(b << 12) + ib + j];
    }
    __syncthreads();

    const int w = tid >> 5;                            // warp 0..7
    const int l = tid & 31;                            // lane = W_q row
    const int gbase = c * IND + ib + (w << 7);         // group index base

    const int4*   qp = reinterpret_cast<const int4*>(Wq + (long)l * GCNT + gbase);
    const float4* sp = reinterpret_cast<const float4*>(scale + gbase);
    const float4* zp = reinterpret_cast<const float4*>(zero  + gbase);
    const unsigned long long* xd = sm + (w << 9);      // w*128 i * 4 pairs

    unsigned long long a0=0,a1=0,a2=0,a3=0;            // hi-nibble row, 4 batch pairs
    unsigned long long a4=0,a5=0,a6=0,a7=0;            // lo-nibble row

#define PROC(QJ, SJ, ZJ, OFF)                                                   \
    {                                                                           \
        float t  = -(ZJ) * (SJ);                                                \
        float fh = __int_as_float((((QJ) >> 4) & 0xF) | 0x4B000000) - 8388608.0f;\
        float fl = __int_as_float(((QJ) & 0xF)        | 0x4B000000) - 8388608.0f;\
        float wh = fmaf(fh, (SJ), t);                                           \
        float wl = fmaf(fl, (SJ), t);                                           \
        unsigned long long wh2 = pack2(wh), wl2 = pack2(wl);                    \
        unsigned long long x01 = xi[(OFF)+0], x23 = xi[(OFF)+1];                \
        unsigned long long x45 = xi[(OFF)+2], x67 = xi[(OFF)+3];                \
        fma2(a0, x01, wh2); fma2(a1, x23, wh2);                                 \
        fma2(a2, x45, wh2); fma2(a3, x67, wh2);                                 \
        fma2(a4, x01, wl2); fma2(a5, x23, wl2);                                 \
        fma2(a6, x45, wl2); fma2(a7, x67, wl2);                                 \
    }

    #pragma unroll 4
    for (int it = 0; it < 32; ++it) {                  // 32 x 4 i = 128 i per lane
        const int4   q = __ldg(qp + it);
        const float4 s = __ldg(sp + it);
        const float4 z = __ldg(zp + it);
        const unsigned long long* xi = xd + (it << 4); // 16 pairs per iter
        PROC(q.x, s.x, z.x, 0)
        PROC(q.y, s.y, z.y, 4)
        PROC(q.z, s.z, z.z, 8)
        PROC(q.w, s.w, z.w, 12)
    }
#undef PROC

    // Cross-warp reduction in smem: warps share the same lane->row mapping.
    __syncthreads();
    unsigned long long* red = sm;                      // 2048 ull = 16 KB
    const int base = tid << 3;
    red[base+0]=a0; red[base+1]=a1; red[base+2]=a2; red[base+3]=a3;
    red[base+4]=a4; red[base+5]=a5; red[base+6]=a6; red[base+7]=a7;
    __syncthreads();

    const int l2 = tid >> 3;                           // row-lane 0..31
    const int k  = tid & 7;                            // 0..3 hi pairs, 4..7 lo pairs
    float sx = 0.f, sy = 0.f;
    #pragma unroll
    for (int ww = 0; ww < 8; ++ww) {
        unsigned long long v = red[(ww << 8) + (l2 << 3) + k];
        float2 f = *reinterpret_cast<float2*>(&v);
        sx += f.x; sy += f.y;
    }
    const int o = (l2 + ((k >> 2) << 5)) * CDIM + c;   // output row
    const int p = k & 3;                               // batch pair
    atomicAdd(out + (2*p    ) * OUTD + o, sx);
    atomicAdd(out + (2*p + 1) * OUTD + o, sy);
}

// ---------------------------------------------------------------------------
extern "C" void kernel_launch(void* const* d_in, const int* in_sizes, int n_in,
                              void* d_out, int out_size) {
    const int*   Wq    = (const int*)  d_in[0];
    const float* scale = (const float*)d_in[1];
    const float* zero  = (const float*)d_in[2];
    const float* x     = (const float*)d_in[3];
    const float* bias  = (const float*)d_in[4];
    float* out = (float*)d_out;

    init_out_kernel<<<(NBATCH * OUTD + 255) / 256, 256>>>(bias, out);
    hqq_gemv_kernel<<<CDIM * 4, 256>>>(Wq, scale, zero, x, out);
}

// round 3
// speedup vs baseline: 1.0818x; 1.0818x over previous
#include <cuda_runtime.h>
#include <cstdint>

#define OUTD 11008
#define IND  4096
#define GCNT 704512
#define CDIM 172
#define NB   8
#define ICHUNK 512
#define NIT  (ICHUNK / 32)

typedef unsigned long long ull;

// ---------------------------------------------------------------------------
__global__ void init_out_kernel(const float* __restrict__ bias,
                                float* __restrict__ out) {
    int idx = blockIdx.x * blockDim.x + threadIdx.x;
    if (idx < NB * OUTD) out[idx] = bias[idx % OUTD];
}

// packed f32x2 helpers (sm_100+)
__device__ __forceinline__ void fma2(ull& acc, ull a, ull b) {
    asm("fma.rn.f32x2 %0, %1, %2, %0;" : "+l"(acc) : "l"(a), "l"(b));
}
__device__ __forceinline__ ull add2(ull a, ull b) {
    ull r; asm("add.rn.f32x2 %0, %1, %2;" : "=l"(r) : "l"(a), "l"(b)); return r;
}
__device__ __forceinline__ ull pack2(float v) {
    ull r; asm("mov.b64 %0, {%1, %1};" : "=l"(r) : "f"(v)); return r;
}
__device__ __forceinline__ ull pack2f(float a, float b) {
    ull r; asm("mov.b64 %0, {%1, %2};" : "=l"(r) : "f"(a), "f"(b)); return r;
}

// ---------------------------------------------------------------------------
// Block = (c, i-chunk of 512). Warp w owns Wq rows 4w..4w+3 (=> 8 output rows).
// Lane = i offset within a 32-wide stripe -> all global loads coalesced.
// ---------------------------------------------------------------------------
__global__ __launch_bounds__(256, 2) void hqq_gemv_kernel(
    const int*   __restrict__ Wq,     // [32, 704512] int32 (one byte per elem)
    const float* __restrict__ scale,  // [704512]
    const float* __restrict__ zero,   // [704512]
    const float* __restrict__ x,      // [8, 4096]
    float*       __restrict__ out)    // [8, 11008]
{
    __shared__ ull xsm[4 * ICHUNK];                    // xp[pp][j], 16 KB

    const int tid = threadIdx.x;
    const int c   = blockIdx.x >> 3;                   // 0..171
    const int ib  = (blockIdx.x & 7) * ICHUNK;

    // Stage x as 4 batch-pair planes: xsm[pp*512 + j] = {x[2pp][ib+j], x[2pp+1][ib+j]}
    for (int k = tid; k < 4 * ICHUNK; k += 256) {
        int pp = k >> 9, j = k & (ICHUNK - 1);
        float lo = x[(2 * pp)     * IND + ib + j];
        float hi = x[(2 * pp + 1) * IND + ib + j];
        xsm[k] = pack2f(lo, hi);
    }
    __syncthreads();

    const int w    = tid >> 5;                         // warp 0..7
    const int l    = tid & 31;
    const int wrow = w << 2;                           // Wq rows wrow..wrow+3
    const int g0   = c * IND + ib + l;

    const int*   q0p = Wq + (long)(wrow + 0) * GCNT + g0;
    const int*   q1p = Wq + (long)(wrow + 1) * GCNT + g0;
    const int*   q2p = Wq + (long)(wrow + 2) * GCNT + g0;
    const int*   q3p = Wq + (long)(wrow + 3) * GCNT + g0;
    const float* sp  = scale + g0;
    const float* zp  = zero  + g0;

    ull acc[32];
    #pragma unroll
    for (int i = 0; i < 32; ++i) acc[i] = 0ull;

    // prefetch iter 0
    float s_c = __ldg(sp), z_c = __ldg(zp);
    int qa = __ldg(q0p), qb = __ldg(q1p), qc = __ldg(q2p), qd = __ldg(q3p);

    #pragma unroll 2
    for (int it = 0; it < NIT; ++it) {
        // prefetch next stripe (clamped; extra in-bounds load on last iter)
        const int off = (it + 1 < NIT) ? (it + 1) * 32 : 0;
        float s_n = __ldg(sp + off), z_n = __ldg(zp + off);
        int qan = __ldg(q0p + off), qbn = __ldg(q1p + off);
        int qcn = __ldg(q2p + off), qdn = __ldg(q3p + off);

        // per-group constants (shared by 4 rowpairs)
        const float t   = -z_c * s_c;                  // -z*s  (small magnitude)
        const float s16 = s_c * 0.0625f;               // exact pow2 scaling

        // x batch pairs for this lane's group (4x LDS.64, conflict-free)
        const ull* xr = xsm + it * 32 + l;
        const ull x01 = xr[0], x23 = xr[ICHUNK], x45 = xr[2 * ICHUNK], x67 = xr[3 * ICHUNK];

        // Exact nibble extraction: f = int_as_float(nib|0x4B000000) - 8388608
        // gives nl (resp. 16*nh) EXACTLY; then one fma with small operands.
#define DOROW(QV, RP)                                                          \
        {                                                                      \
            float fl = __int_as_float(((QV) & 0x0F) | 0x4B000000) - 8388608.f; \
            float fh = __int_as_float(((QV) & 0xF0) | 0x4B000000) - 8388608.f; \
            float wl = fmaf(fl, s_c, t);                                       \
            float wh = fmaf(fh, s16, t);                                       \
            ull wh2 = pack2(wh), wl2 = pack2(wl);                              \
            fma2(acc[(RP)*8 + 0], x01, wh2); fma2(acc[(RP)*8 + 1], x23, wh2);  \
            fma2(acc[(RP)*8 + 2], x45, wh2); fma2(acc[(RP)*8 + 3], x67, wh2);  \
            fma2(acc[(RP)*8 + 4], x01, wl2); fma2(acc[(RP)*8 + 5], x23, wl2);  \
            fma2(acc[(RP)*8 + 6], x45, wl2); fma2(acc[(RP)*8 + 7], x67, wl2);  \
        }
        DOROW(qa, 0) DOROW(qb, 1) DOROW(qc, 2) DOROW(qd, 3)
#undef DOROW

        s_c = s_n; z_c = z_n; qa = qan; qb = qbn; qc = qcn; qd = qdn;
    }

    // Butterfly halving exchange: 32 f32x2 per lane -> 1 f32x2 per lane,
    // each summed over all 32 lanes. Lane l ends with original index l:
    // rp = l>>3, rowhalf = (l>>2)&1 (0=hi,1=lo), batchpair = l&3.
    #pragma unroll
    for (int d = 16; d >= 1; d >>= 1) {
        const bool up = (l & d) != 0;
        #pragma unroll
        for (int k = 0; k < d; ++k) {
            ull send = up ? acc[k] : acc[k + d];
            ull got  = __shfl_xor_sync(0xffffffffu, send, d);
            ull keep = up ? acc[k + d] : acc[k];
            acc[k] = add2(keep, got);
        }
    }

    float fx, fy;
    asm("mov.b64 {%0, %1}, %2;" : "=f"(fx), "=f"(fy) : "l"(acc[0]));
    const int rp = l >> 3, rh = (l >> 2) & 1, p = l & 3;
    const int o  = (wrow + rp + rh * 32) * CDIM + c;
    atomicAdd(out + (2 * p)     * OUTD + o, fx);
    atomicAdd(out + (2 * p + 1) * OUTD + o, fy);
}

// ---------------------------------------------------------------------------
extern "C" void kernel_launch(void* const* d_in, const int* in_sizes, int n_in,
                              void* d_out, int out_size) {
    const int*   Wq    = (const int*)  d_in[0];
    const float* scale = (const float*)d_in[1];
    const float* zero  = (const float*)d_in[2];
    const float* x     = (const float*)d_in[3];
    const float* bias  = (const float*)d_in[4];
    float* out = (float*)d_out;

    init_out_kernel<<<(NB * OUTD + 255) / 256, 256>>>(bias, out);
    hqq_gemv_kernel<<<CDIM * (IND / ICHUNK), 256>>>(Wq, scale, zero, x, out);
}